// round 7
// baseline (speedup 1.0000x reference)
#include <cuda_runtime.h>
#include <cuda_bf16.h>

#define BATCH 512
#define NIN   64
#define ADIM  64

typedef unsigned long long ull;

// ---------------- device scratch (static, no allocation) -------------------
__device__ float4 g_P4[31 * 4 * 1024];   // pair products, row-major fp32 [mat][a*16+q]
__device__ uint4  g_Q4[248 * 512];       // quads(240)+triples(8), bf16, chunk layout:
                                         //   mat*512 + q*64 + row ; uint4 = row's k=8q..8q+7

#define AST4 17                          // A row stride in float4 units (68 floats)

// ---- packed f32x2 helpers (sm_103a) ---------------------------------------
__device__ __forceinline__ void ffma2(ull& d, ull a, ull b) {
    asm("fma.rn.f32x2 %0, %1, %2, %0;" : "+l"(d) : "l"(a), "l"(b));
}
__device__ __forceinline__ ull pk2(float x, float y) {
    ull r; asm("mov.b64 %0, {%1, %2};" : "=l"(r) : "f"(x), "f"(y)); return r;
}
__device__ __forceinline__ void up2(ull v, float& x, float& y) {
    asm("mov.b64 {%0, %1}, %2;" : "=f"(x), "=f"(y) : "l"(v));
}

// 64x64x64 GEMM consumer: A in padded-f4 smem (stride AST4), B row-major f4.
// thread = (a = tid&63, seg = tid>>6); computes C[a][seg*8 .. seg*8+7].
// Depth-2 software pipeline on B (LDS.128 pairs) + 1-group-ahead A prefetch.
__device__ __forceinline__ void gemm_inner(const float4* sA4, const float4* sB4,
                                           int a, int seg, float* out8) {
    ull c0 = 0, c1 = 0, c2 = 0, c3 = 0;
    const float4*     ap = sA4 + a * AST4;
    const ulonglong2* bp = reinterpret_cast<const ulonglong2*>(sB4 + seg * 2);
    // B row stride = 16 float4 = 16 x 16B units

    ulonglong2 bb[2][2];
    bb[0][0] = bp[0];       bb[0][1] = bp[1];
    bb[1][0] = bp[16];      bb[1][1] = bp[17];
    float4 av = ap[0], avn = av;

    #pragma unroll
    for (int j = 0; j < 64; ++j) {
        int jj = j & 3;
        if (jj == 0 && j + 4 < 64) avn = ap[(j >> 2) + 1];
        float s = (jj == 0) ? av.x : (jj == 1) ? av.y : (jj == 2) ? av.z : av.w;
        ull ss = pk2(s, s);
        ulonglong2 t0 = bb[j & 1][0], t1 = bb[j & 1][1];
        if (j + 2 < 64) {
            bb[j & 1][0] = bp[(j + 2) * 16];
            bb[j & 1][1] = bp[(j + 2) * 16 + 1];
        }
        ffma2(c0, ss, t0.x);
        ffma2(c1, ss, t0.y);
        ffma2(c2, ss, t1.x);
        ffma2(c3, ss, t1.y);
        if (jj == 3) av = avn;
    }
    up2(c0, out8[0], out8[1]);
    up2(c1, out8[2], out8[3]);
    up2(c2, out8[4], out8[5]);
    up2(c3, out8[6], out8[7]);
}

// ---------------------------------------------------------------------------
// Kernel 1: fused prep+pair. CTA (t,vv): A=W_{2t}^{c0}, B=W_{2t+1}^{c1} inline
// from theta/u, then P = A@B. grid=124, block=512.
// W_i^c[a,k] = sigmoid_c(theta[i,a,k]) * softmax(u[i])[k]
// ---------------------------------------------------------------------------
__global__ void __launch_bounds__(512) k_pair(const float* __restrict__ theta,
                                              const float* __restrict__ u) {
    __shared__ __align__(16) float sA[64 * AST4 * 4];
    __shared__ __align__(16) float sB[4096];
    __shared__ float expa[2][64];

    int blk = blockIdx.x, tid = threadIdx.x;
    int t = blk >> 2, vv = blk & 3;
    int i0 = 2 * t, i1 = 2 * t + 1, c0 = vv >> 1, c1 = vv & 1;
    int wid = tid >> 5, lane = tid & 31;

    if (wid < 2) {                               // softmax(u[i0]), softmax(u[i1])
        int i = i0 + wid;
        float u0 = u[i * 64 + lane], u1 = u[i * 64 + 32 + lane];
        float mm = fmaxf(u0, u1);
        #pragma unroll
        for (int o = 16; o; o >>= 1) mm = fmaxf(mm, __shfl_xor_sync(0xffffffffu, mm, o));
        float ss = __expf(u0 - mm) + __expf(u1 - mm);
        #pragma unroll
        for (int o = 16; o; o >>= 1) ss += __shfl_xor_sync(0xffffffffu, ss, o);
        float lse = mm + __logf(ss);
        expa[wid][lane]      = __expf(u0 - lse);
        expa[wid][lane + 32] = __expf(u1 - lse);
    }
    __syncthreads();

    const float4* th4 = reinterpret_cast<const float4*>(theta);
    float4* sA4 = reinterpret_cast<float4*>(sA);
    float4* sB4 = reinterpret_cast<float4*>(sB);
    #pragma unroll
    for (int r = 0; r < 2; ++r) {
        int idx4 = tid + 512 * r;                // float4 index 0..1023
        int row = idx4 >> 4, q = idx4 & 15;
        int k0 = q * 4;
        float4 ta = th4[i0 * 1024 + idx4];
        float4 oa;
        { float s = __fdividef(1.0f, 1.0f + __expf(-ta.x)); oa.x = (c0 ? s : 1.0f - s) * expa[0][k0 + 0]; }
        { float s = __fdividef(1.0f, 1.0f + __expf(-ta.y)); oa.y = (c0 ? s : 1.0f - s) * expa[0][k0 + 1]; }
        { float s = __fdividef(1.0f, 1.0f + __expf(-ta.z)); oa.z = (c0 ? s : 1.0f - s) * expa[0][k0 + 2]; }
        { float s = __fdividef(1.0f, 1.0f + __expf(-ta.w)); oa.w = (c0 ? s : 1.0f - s) * expa[0][k0 + 3]; }
        sA4[row * AST4 + q] = oa;
        float4 tb = th4[i1 * 1024 + idx4];
        float4 ob;
        { float s = __fdividef(1.0f, 1.0f + __expf(-tb.x)); ob.x = (c1 ? s : 1.0f - s) * expa[1][k0 + 0]; }
        { float s = __fdividef(1.0f, 1.0f + __expf(-tb.y)); ob.y = (c1 ? s : 1.0f - s) * expa[1][k0 + 1]; }
        { float s = __fdividef(1.0f, 1.0f + __expf(-tb.z)); ob.z = (c1 ? s : 1.0f - s) * expa[1][k0 + 2]; }
        { float s = __fdividef(1.0f, 1.0f + __expf(-tb.w)); ob.w = (c1 ? s : 1.0f - s) * expa[1][k0 + 3]; }
        sB4[idx4] = ob;
    }
    __syncthreads();

    int a = tid & 63, seg = tid >> 6;
    float acc[8];
    gemm_inner(sA4, sB4, a, seg, acc);

    float4* C4 = g_P4 + blk * 1024;
    C4[a * 16 + seg * 2]     = make_float4(acc[0], acc[1], acc[2], acc[3]);
    C4[a * 16 + seg * 2 + 1] = make_float4(acc[4], acc[5], acc[6], acc[7]);
}

// ---------------------------------------------------------------------------
// Kernel 2: quads Q = P_{2t}^{v>>2} @ P_{2t+1}^{v&3} (blk<240);
//           triples T = P_30^{v>>1} @ W62^{v&1} (blk 240..247, W62 inline).
// Output bf16 chunk layout for k_main. grid=248, block=512.
// ---------------------------------------------------------------------------
__global__ void __launch_bounds__(512) k_quad(const float* __restrict__ theta,
                                              const float* __restrict__ u) {
    __shared__ __align__(16) float sA[64 * AST4 * 4];
    __shared__ __align__(16) float sB[4096];
    __shared__ float expa[64];
    int blk = blockIdx.x, tid = threadIdx.x;

    float4* sA4 = reinterpret_cast<float4*>(sA);
    float4* sB4 = reinterpret_cast<float4*>(sB);

    if (blk < 240) {
        int t = blk >> 4, v = blk & 15;
        const float4* A4 = g_P4 + ((2 * t)     * 4 + (v >> 2)) * 1024;
        const float4* B4 = g_P4 + ((2 * t + 1) * 4 + (v & 3))  * 1024;
        #pragma unroll
        for (int r = 0; r < 2; ++r) {
            int idx4 = tid + 512 * r;            // = row*16 + q
            int row = idx4 >> 4, q = idx4 & 15;
            sA4[row * AST4 + q] = A4[idx4];
            sB4[idx4] = B4[idx4];
        }
    } else {
        int v = blk - 240;
        const float4* A4 = g_P4 + (30 * 4 + (v >> 1)) * 1024;
        #pragma unroll
        for (int r = 0; r < 2; ++r) {
            int idx4 = tid + 512 * r;
            int row = idx4 >> 4, q = idx4 & 15;
            sA4[row * AST4 + q] = A4[idx4];
        }
        int c = v & 1;
        if (tid < 32) {                          // softmax(u[62])
            float u0 = u[62 * 64 + tid], u1 = u[62 * 64 + 32 + tid];
            float mm = fmaxf(u0, u1);
            #pragma unroll
            for (int o = 16; o; o >>= 1) mm = fmaxf(mm, __shfl_xor_sync(0xffffffffu, mm, o));
            float ss = __expf(u0 - mm) + __expf(u1 - mm);
            #pragma unroll
            for (int o = 16; o; o >>= 1) ss += __shfl_xor_sync(0xffffffffu, ss, o);
            float lse = mm + __logf(ss);
            expa[tid]      = __expf(u0 - lse);
            expa[tid + 32] = __expf(u1 - lse);
        }
        __syncthreads();
        const float4* th4 = reinterpret_cast<const float4*>(theta);
        #pragma unroll
        for (int r = 0; r < 2; ++r) {
            int idx4 = tid + 512 * r;
            int k0 = (idx4 * 4) & 63;
            float4 tb = th4[62 * 1024 + idx4];
            float4 ob;
            { float s = __fdividef(1.0f, 1.0f + __expf(-tb.x)); ob.x = (c ? s : 1.0f - s) * expa[k0 + 0]; }
            { float s = __fdividef(1.0f, 1.0f + __expf(-tb.y)); ob.y = (c ? s : 1.0f - s) * expa[k0 + 1]; }
            { float s = __fdividef(1.0f, 1.0f + __expf(-tb.z)); ob.z = (c ? s : 1.0f - s) * expa[k0 + 2]; }
            { float s = __fdividef(1.0f, 1.0f + __expf(-tb.w)); ob.w = (c ? s : 1.0f - s) * expa[k0 + 3]; }
            sB4[idx4] = ob;
        }
    }
    __syncthreads();

    int a = tid & 63, seg = tid >> 6;
    float acc[8];
    gemm_inner(sA4, sB4, a, seg, acc);

    __nv_bfloat162 p0 = __floats2bfloat162_rn(acc[0], acc[1]);
    __nv_bfloat162 p1 = __floats2bfloat162_rn(acc[2], acc[3]);
    __nv_bfloat162 p2 = __floats2bfloat162_rn(acc[4], acc[5]);
    __nv_bfloat162 p3 = __floats2bfloat162_rn(acc[6], acc[7]);
    uint4 uo;
    uo.x = *reinterpret_cast<unsigned*>(&p0);
    uo.y = *reinterpret_cast<unsigned*>(&p1);
    uo.z = *reinterpret_cast<unsigned*>(&p2);
    uo.w = *reinterpret_cast<unsigned*>(&p3);
    g_Q4[blk * 512 + seg * 64 + a] = uo;
}

// ---------------------------------------------------------------------------
// Kernel 3: per-batch stabilized log-semiring chain, 16 steps. (unchanged)
// ---------------------------------------------------------------------------
__device__ __forceinline__ int matq(unsigned long long bits, int t) {
    unsigned nib = (unsigned)(bits >> (4 * t)) & 0xFu;
    unsigned v = ((nib & 1u) << 3) | ((nib & 2u) << 1) | ((nib & 4u) >> 1) | ((nib & 8u) >> 3);
    return t * 16 + (int)v;
}

__device__ __forceinline__ float dotstep(const uint4* wr, const float4* e4) {
    float a0 = 0.f, a1 = 0.f, a2 = 0.f, a3 = 0.f;
    float a4 = 0.f, a5 = 0.f, a6 = 0.f, a7 = 0.f;
    #pragma unroll
    for (int q = 0; q < 8; ++q) {
        float4 e0 = e4[2 * q], e1 = e4[2 * q + 1];
        uint4 uw = wr[q];
        a0 = fmaf(__uint_as_float(uw.x << 16),          e0.x, a0);
        a1 = fmaf(__uint_as_float(uw.x & 0xffff0000u),  e0.y, a1);
        a2 = fmaf(__uint_as_float(uw.y << 16),          e0.z, a2);
        a3 = fmaf(__uint_as_float(uw.y & 0xffff0000u),  e0.w, a3);
        a4 = fmaf(__uint_as_float(uw.z << 16),          e1.x, a4);
        a5 = fmaf(__uint_as_float(uw.z & 0xffff0000u),  e1.y, a5);
        a6 = fmaf(__uint_as_float(uw.w << 16),          e1.z, a6);
        a7 = fmaf(__uint_as_float(uw.w & 0xffff0000u),  e1.w, a7);
    }
    return ((a0 + a1) + (a2 + a3)) + ((a4 + a5) + (a6 + a7));
}

__global__ void __launch_bounds__(64) k_main(const float* __restrict__ x,
                                             const float* __restrict__ theta,
                                             float* __restrict__ out) {
    int tid = threadIdx.x, w = tid >> 5, l = tid & 31;
    int b = blockIdx.x;

    __shared__ __align__(16) float se[2][64];
    __shared__ float red[2];
    __shared__ unsigned sbits[2];

    float xa = x[b * 64 + tid];
    unsigned bal = __ballot_sync(0xffffffffu, xa != 0.0f);
    if (l == 0) sbits[w] = bal;
    __syncthreads();
    unsigned long long bits =
        ((unsigned long long)sbits[1] << 32) | (unsigned long long)sbits[0];

    // v init: log p(x63 | a, col 0)
    int c63 = (int)(bits >> 63) & 1;
    float t63 = theta[63 * 4096 + tid * 64];
    float v = (c63 ? t63 : 0.0f) - fmaxf(t63, 0.0f)
            - __logf(1.0f + __expf(-fabsf(t63)));

    // prefetch step 0 (triple)
    int m0 = 240 + (((int)(bits >> 60) & 1) << 2)
                 + (((int)(bits >> 61) & 1) << 1)
                 +  ((int)(bits >> 62) & 1);
    uint4 wrA[8], wrB[8];
    {
        const uint4* base = g_Q4 + m0 * 512;
        #pragma unroll
        for (int q = 0; q < 8; ++q) wrA[q] = base[q * 64 + tid];
    }

    float m = 0.0f;
    #pragma unroll 1
    for (int sp = 0; sp < 8; ++sp) {
        // ---- even step: compute with wrA, prefetch wrB, refresh max ----
        {
            const uint4* nb = g_Q4 + matq(bits, 14 - 2 * sp) * 512;
            #pragma unroll
            for (int q = 0; q < 8; ++q) wrB[q] = nb[q * 64 + tid];

            float wm = v;
            #pragma unroll
            for (int o = 16; o; o >>= 1) wm = fmaxf(wm, __shfl_xor_sync(0xffffffffu, wm, o));
            if (l == 0) red[w] = wm;
            __syncthreads();
            m = fmaxf(red[0], red[1]);
            se[0][tid] = __expf(v - m);
            __syncthreads();
            v = __logf(dotstep(wrA, reinterpret_cast<const float4*>(se[0]))) + m;
        }
        // ---- odd step: compute with wrB, prefetch wrA, stale max ----
        {
            if (sp < 7) {
                const uint4* nb = g_Q4 + matq(bits, 13 - 2 * sp) * 512;
                #pragma unroll
                for (int q = 0; q < 8; ++q) wrA[q] = nb[q * 64 + tid];
            }
            se[1][tid] = __expf(v - m);
            __syncthreads();
            v = __logf(dotstep(wrB, reinterpret_cast<const float4*>(se[1]))) + m;
        }
    }

    out[b * 64 + tid] = v;
}

// ---------------------------------------------------------------------------
extern "C" void kernel_launch(void* const* d_in, const int* in_sizes, int n_in,
                              void* d_out, int out_size) {
    const float* x     = nullptr;
    const float* theta = nullptr;
    const float* u     = nullptr;
    for (int i = 0; i < n_in; ++i) {
        if      (in_sizes[i] == BATCH * NIN)       x     = (const float*)d_in[i];
        else if (in_sizes[i] == NIN * ADIM * ADIM) theta = (const float*)d_in[i];
        else if (in_sizes[i] == (NIN - 1) * ADIM)  u     = (const float*)d_in[i];
    }

    k_pair<<<124, 512>>>(theta, u);
    k_quad<<<248, 512>>>(theta, u);
    k_main<<<BATCH, 64>>>(x, theta, (float*)d_out);
}